// round 14
// baseline (speedup 1.0000x reference)
#include <cuda_runtime.h>
#include <cuda_bf16.h>
#include <cstdint>

#define N_NODES 50000
#define N_EDGES 800000
#define D 256
#define BN_EPS 1e-5f
#define SCAN_NB 196            // ceil(50000/256)

// ---------------- scratch (device globals: allocation-free) ----------------
__device__ int   g_cnt[N_NODES];
__device__ int   g_fill[N_NODES];       // CSR fill cursors (pre-loaded with offsets)
__device__ int   g_off[N_NODES];
__device__ int   g_csr_src[N_EDGES];
__device__ float g_dinv[N_NODES];
__device__ int   g_scan_state[SCAN_NB]; // 0=pending 1=aggregate 2=inclusive
__device__ int   g_scan_agg[SCAN_NB];
__device__ int   g_scan_inc[SCAN_NB];
__device__ __nv_bfloat16 g_whi[D * D];
__device__ __nv_bfloat16 g_wlo[D * D];
__device__ float g_hprime[(size_t)N_NODES * D];
__device__ float g_agg[(size_t)N_NODES * D];
__device__ float g_sum[D];
__device__ float g_sumsq[D];

__device__ __forceinline__ unsigned pack_bf2(float a, float b) {
    __nv_bfloat162 p = __floats2bfloat162_rn(a, b);
    return *reinterpret_cast<unsigned*>(&p);
}

// ---------------- 1) init counters + scan state + BN sums + W split -------
__global__ void init_kernel(const float* __restrict__ W) {
    int i = blockIdx.x * blockDim.x + threadIdx.x;
    if (i < N_NODES) g_cnt[i] = 0;
    if (i < SCAN_NB) g_scan_state[i] = 0;
    if (i < D) { g_sum[i] = 0.0f; g_sumsq[i] = 0.0f; }
    if (i < D * D / 4) {
        float4 v = reinterpret_cast<const float4*>(W)[i];
        float hx = __bfloat162float(__float2bfloat16(v.x));
        float hy = __bfloat162float(__float2bfloat16(v.y));
        float hz = __bfloat162float(__float2bfloat16(v.z));
        float hw = __bfloat162float(__float2bfloat16(v.w));
        uint2 hi = make_uint2(pack_bf2(v.x, v.y), pack_bf2(v.z, v.w));
        uint2 lo = make_uint2(pack_bf2(v.x - hx, v.y - hy), pack_bf2(v.z - hz, v.w - hw));
        reinterpret_cast<uint2*>(g_whi)[i] = hi;
        reinterpret_cast<uint2*>(g_wlo)[i] = lo;
    }
}

// ---------------- 2) in-degree count (int4 vectorized) --------------------
__global__ void count_kernel(const int* __restrict__ col) {
    int i = blockIdx.x * blockDim.x + threadIdx.x;      // quad index
    if (i >= N_EDGES / 4) return;
    int4 c = reinterpret_cast<const int4*>(col)[i];
    atomicAdd(&g_cnt[c.x], 1);
    atomicAdd(&g_cnt[c.y], 1);
    atomicAdd(&g_cnt[c.z], 1);
    atomicAdd(&g_cnt[c.w], 1);
}

// ---------------- 3) single-pass scan (decoupled lookback) + dinv ---------
__global__ void __launch_bounds__(256) scan_kernel() {
    __shared__ int sm[256];
    __shared__ int s_prefix;
    const int b   = blockIdx.x;
    const int tid = threadIdx.x;
    const int i   = b * 256 + tid;
    int v = (i < N_NODES) ? g_cnt[i] : 0;
    sm[tid] = v;
    __syncthreads();
#pragma unroll
    for (int ofs = 1; ofs < 256; ofs <<= 1) {
        int t = (tid >= ofs) ? sm[tid - ofs] : 0;
        __syncthreads();
        sm[tid] += t;
        __syncthreads();
    }
    const int total = sm[255];

    if (tid == 0) {
        if (b == 0) {
            g_scan_inc[0] = total;
            __threadfence();
            g_scan_state[0] = 2;
            s_prefix = 0;
        } else {
            g_scan_agg[b] = total;
            __threadfence();
            g_scan_state[b] = 1;
            int pref = 0;
            int j = b - 1;
            while (j >= 0) {
                int st;
                do { st = atomicAdd(&g_scan_state[j], 0); } while (st == 0);
                if (st == 2) { pref += atomicAdd(&g_scan_inc[j], 0); break; }
                pref += atomicAdd(&g_scan_agg[j], 0);
                j--;
            }
            g_scan_inc[b] = pref + total;
            __threadfence();
            g_scan_state[b] = 2;
            s_prefix = pref;
        }
    }
    __syncthreads();

    if (i < N_NODES) {
        int off = s_prefix + sm[tid] - v;   // exclusive
        g_off[i]  = off;
        g_fill[i] = off;                    // cursor starts at offset
        g_dinv[i] = rsqrtf((float)(v + 1));
    }
}

// ---------------- 4) fill CSR (cursor = offset+count so far) --------------
__global__ void fill_kernel(const int* __restrict__ row,
                            const int* __restrict__ col) {
    int e = blockIdx.x * blockDim.x + threadIdx.x;
    if (e >= N_EDGES) return;
    int src = row[e];
    int dst = col[e];
    int pos = atomicAdd(&g_fill[dst], 1);
    g_csr_src[pos] = src;
}

// ---------------- 5) tensor-core GEMM: h' = dinv .* (x @ W^T) -------------
// 3xBF16 split on mma.sync.m16n8k16, in-register A split, ldmatrix frags.
// BM=64, BN=128, BK=32. 8 warps: wm = (wid&1)*32, wn = (wid>>1)*32.
#define APAD 40

__device__ __forceinline__ void mma_bf16(float* c, const unsigned* a, const unsigned* b) {
    asm volatile(
        "mma.sync.aligned.m16n8k16.row.col.f32.bf16.bf16.f32 "
        "{%0,%1,%2,%3}, {%4,%5,%6,%7}, {%8,%9}, {%0,%1,%2,%3};"
        : "+f"(c[0]), "+f"(c[1]), "+f"(c[2]), "+f"(c[3])
        : "r"(a[0]), "r"(a[1]), "r"(a[2]), "r"(a[3]), "r"(b[0]), "r"(b[1]));
}
__device__ __forceinline__ void ldmx4(unsigned* r, unsigned addr) {
    asm volatile("ldmatrix.sync.aligned.m8n8.x4.shared.b16 {%0,%1,%2,%3}, [%4];"
                 : "=r"(r[0]), "=r"(r[1]), "=r"(r[2]), "=r"(r[3]) : "r"(addr));
}
__device__ __forceinline__ void ldmx2(unsigned* r, unsigned addr) {
    asm volatile("ldmatrix.sync.aligned.m8n8.x2.shared.b16 {%0,%1}, [%2];"
                 : "=r"(r[0]), "=r"(r[1]) : "r"(addr));
}
__device__ __forceinline__ unsigned s2u(const void* p) {
    return (unsigned)__cvta_generic_to_shared(p);
}
__device__ __forceinline__ void split4(float4 v, uint2& hi, uint2& lo) {
    float hx = __bfloat162float(__float2bfloat16(v.x));
    float hy = __bfloat162float(__float2bfloat16(v.y));
    float hz = __bfloat162float(__float2bfloat16(v.z));
    float hw = __bfloat162float(__float2bfloat16(v.w));
    hi = make_uint2(pack_bf2(v.x, v.y), pack_bf2(v.z, v.w));
    lo = make_uint2(pack_bf2(v.x - hx, v.y - hy), pack_bf2(v.z - hz, v.w - hw));
}

__global__ void __launch_bounds__(256) gemm_kernel(const float* __restrict__ x) {
    __shared__ __nv_bfloat16 As_hi[64][APAD];
    __shared__ __nv_bfloat16 As_lo[64][APAD];
    __shared__ __nv_bfloat16 Bs_hi[128][APAD];
    __shared__ __nv_bfloat16 Bs_lo[128][APAD];

    const int brow = blockIdx.x * 64;
    const int bcol = blockIdx.y * 128;
    const int tid  = threadIdx.x;
    const int lane = tid & 31;
    const int wid  = tid >> 5;
    const int wm   = (wid & 1) * 32;
    const int wn   = (wid >> 1) * 32;
    const int lr   = lane & 7;
    const int grp  = lane >> 3;

    float acc[2][4][4];
#pragma unroll
    for (int mi = 0; mi < 2; mi++)
#pragma unroll
        for (int ni = 0; ni < 4; ni++)
#pragma unroll
            for (int r = 0; r < 4; r++) acc[mi][ni][r] = 0.0f;

    const int arow = tid >> 2;
    const int acol = (tid & 3) * 8;
    const bool avalid = (brow + arow < N_NODES);
    const float* xrow = x + (size_t)(brow + arow) * D + acol;
    const int br0 = tid >> 2,          bc0 = (tid & 3) * 8;
    const int br1 = (tid + 256) >> 2,  bc1 = ((tid + 256) & 3) * 8;
    const __nv_bfloat16* wh0 = g_whi + (size_t)(bcol + br0) * D + bc0;
    const __nv_bfloat16* wl0 = g_wlo + (size_t)(bcol + br0) * D + bc0;
    const __nv_bfloat16* wh1 = g_whi + (size_t)(bcol + br1) * D + bc1;
    const __nv_bfloat16* wl1 = g_wlo + (size_t)(bcol + br1) * D + bc1;

    const float4 zf4 = make_float4(0.f, 0.f, 0.f, 0.f);
    float4 sa0, sa1;
    uint4  sbh0, sbl0, sbh1, sbl1;

    sa0  = avalid ? *reinterpret_cast<const float4*>(xrow)     : zf4;
    sa1  = avalid ? *reinterpret_cast<const float4*>(xrow + 4) : zf4;
    sbh0 = *reinterpret_cast<const uint4*>(wh0);
    sbl0 = *reinterpret_cast<const uint4*>(wl0);
    sbh1 = *reinterpret_cast<const uint4*>(wh1);
    sbl1 = *reinterpret_cast<const uint4*>(wl1);

    for (int kb = 0; kb < D; kb += 32) {
        {
            uint2 h0, l0, h1, l1;
            split4(sa0, h0, l0);
            split4(sa1, h1, l1);
            *reinterpret_cast<uint4*>(&As_hi[arow][acol]) = make_uint4(h0.x, h0.y, h1.x, h1.y);
            *reinterpret_cast<uint4*>(&As_lo[arow][acol]) = make_uint4(l0.x, l0.y, l1.x, l1.y);
            *reinterpret_cast<uint4*>(&Bs_hi[br0][bc0]) = sbh0;
            *reinterpret_cast<uint4*>(&Bs_lo[br0][bc0]) = sbl0;
            *reinterpret_cast<uint4*>(&Bs_hi[br1][bc1]) = sbh1;
            *reinterpret_cast<uint4*>(&Bs_lo[br1][bc1]) = sbl1;
        }
        __syncthreads();

        if (kb + 32 < D) {
            int nk = kb + 32;
            sa0  = avalid ? *reinterpret_cast<const float4*>(xrow + nk)     : zf4;
            sa1  = avalid ? *reinterpret_cast<const float4*>(xrow + nk + 4) : zf4;
            sbh0 = *reinterpret_cast<const uint4*>(wh0 + nk);
            sbl0 = *reinterpret_cast<const uint4*>(wl0 + nk);
            sbh1 = *reinterpret_cast<const uint4*>(wh1 + nk);
            sbl1 = *reinterpret_cast<const uint4*>(wl1 + nk);
        }

#pragma unroll
        for (int kk = 0; kk < 32; kk += 16) {
            unsigned ahi[2][4], alo[2][4], bhi[4][2], blo[4][2];
            const int ar = ((grp & 1) << 3) + lr;
            const int ac = kk + ((grp >> 1) << 3);
#pragma unroll
            for (int mi = 0; mi < 2; mi++) {
                ldmx4(ahi[mi], s2u(&As_hi[wm + mi * 16 + ar][ac]));
                ldmx4(alo[mi], s2u(&As_lo[wm + mi * 16 + ar][ac]));
            }
            const int bc = kk + ((lane >> 3) & 1) * 8;
#pragma unroll
            for (int ni = 0; ni < 4; ni++) {
                ldmx2(bhi[ni], s2u(&Bs_hi[wn + ni * 8 + lr][bc]));
                ldmx2(blo[ni], s2u(&Bs_lo[wn + ni * 8 + lr][bc]));
            }
#pragma unroll
            for (int mi = 0; mi < 2; mi++)
#pragma unroll
                for (int ni = 0; ni < 4; ni++) {
                    mma_bf16(acc[mi][ni], ahi[mi], bhi[ni]);
                    mma_bf16(acc[mi][ni], alo[mi], bhi[ni]);
                    mma_bf16(acc[mi][ni], ahi[mi], blo[ni]);
                }
        }
        __syncthreads();
    }

    const int qr = lane >> 2;
    const int qc = lane & 3;
#pragma unroll
    for (int mi = 0; mi < 2; mi++) {
        int r0 = brow + wm + mi * 16 + qr;
        int r1 = r0 + 8;
        float dv0 = (r0 < N_NODES) ? g_dinv[r0] : 0.0f;
        float dv1 = (r1 < N_NODES) ? g_dinv[r1] : 0.0f;
#pragma unroll
        for (int ni = 0; ni < 4; ni++) {
            int c = bcol + wn + ni * 8 + qc * 2;
            if (r0 < N_NODES) {
                float2 v = make_float2(acc[mi][ni][0] * dv0, acc[mi][ni][1] * dv0);
                *reinterpret_cast<float2*>(g_hprime + (size_t)r0 * D + c) = v;
            }
            if (r1 < N_NODES) {
                float2 v = make_float2(acc[mi][ni][2] * dv1, acc[mi][ni][3] * dv1);
                *reinterpret_cast<float2*>(g_hprime + (size_t)r1 * D + c) = v;
            }
        }
    }
}

// ---------------- 6) gather-aggregate + fused BN column stats -------------
__device__ __forceinline__ void acc4(float4& a, const float4& b) {
    a.x += b.x; a.y += b.y; a.z += b.z; a.w += b.w;
}

__global__ void __launch_bounds__(256) aggregate_kernel(const float* __restrict__ bias) {
    __shared__ float s_sum[D];
    __shared__ float s_sq[D];
    const int tid  = threadIdx.x;
    const int lane = tid & 31;
    const int wid  = tid >> 5;
    s_sum[tid] = 0.0f;
    s_sq[tid]  = 0.0f;
    __syncthreads();

    const float4* hp4 = reinterpret_cast<const float4*>(g_hprime);
    float4*       out4 = reinterpret_cast<float4*>(g_agg);
    const float4* b4   = reinterpret_cast<const float4*>(bias);
    const float4 bb0 = b4[lane];
    const float4 bb1 = b4[lane + 32];

    float4 ts0 = make_float4(0.f, 0.f, 0.f, 0.f);
    float4 ts1 = make_float4(0.f, 0.f, 0.f, 0.f);
    float4 tq0 = make_float4(0.f, 0.f, 0.f, 0.f);
    float4 tq1 = make_float4(0.f, 0.f, 0.f, 0.f);

    const int warp0  = blockIdx.x * 8 + wid;
    const int nwarps = gridDim.x * 8;

    for (int c = warp0; c < N_NODES; c += nwarps) {
        float4 a0 = hp4[(size_t)c * 64 + lane];
        float4 a1 = hp4[(size_t)c * 64 + lane + 32];
        float4 e0 = make_float4(0.f, 0.f, 0.f, 0.f);
        float4 e1 = make_float4(0.f, 0.f, 0.f, 0.f);

        const int beg = g_off[c];
        const int end = g_fill[c];          // cursor after fill == off + cnt
        int e = beg;
        for (; e + 1 < end; e += 2) {
            int s0 = g_csr_src[e];
            int s1 = g_csr_src[e + 1];
            const float4* p0 = hp4 + (size_t)s0 * 64;
            const float4* p1 = hp4 + (size_t)s1 * 64;
            float4 u0 = p0[lane], u1 = p0[lane + 32];
            float4 w0 = p1[lane], w1 = p1[lane + 32];
            acc4(a0, u0); acc4(a1, u1);
            acc4(e0, w0); acc4(e1, w1);
        }
        if (e < end) {
            int s0 = g_csr_src[e];
            const float4* p0 = hp4 + (size_t)s0 * 64;
            acc4(a0, p0[lane]); acc4(a1, p0[lane + 32]);
        }
        acc4(a0, e0); acc4(a1, e1);

        const float dv = g_dinv[c];
        a0.x = fmaf(a0.x, dv, bb0.x); a0.y = fmaf(a0.y, dv, bb0.y);
        a0.z = fmaf(a0.z, dv, bb0.z); a0.w = fmaf(a0.w, dv, bb0.w);
        a1.x = fmaf(a1.x, dv, bb1.x); a1.y = fmaf(a1.y, dv, bb1.y);
        a1.z = fmaf(a1.z, dv, bb1.z); a1.w = fmaf(a1.w, dv, bb1.w);

        out4[(size_t)c * 64 + lane]      = a0;
        out4[(size_t)c * 64 + lane + 32] = a1;

        acc4(ts0, a0); acc4(ts1, a1);
        tq0.x = fmaf(a0.x, a0.x, tq0.x); tq0.y = fmaf(a0.y, a0.y, tq0.y);
        tq0.z = fmaf(a0.z, a0.z, tq0.z); tq0.w = fmaf(a0.w, a0.w, tq0.w);
        tq1.x = fmaf(a1.x, a1.x, tq1.x); tq1.y = fmaf(a1.y, a1.y, tq1.y);
        tq1.z = fmaf(a1.z, a1.z, tq1.z); tq1.w = fmaf(a1.w, a1.w, tq1.w);
    }

    const int c0 = 4 * lane;
    atomicAdd(&s_sum[c0 + 0], ts0.x); atomicAdd(&s_sum[c0 + 1], ts0.y);
    atomicAdd(&s_sum[c0 + 2], ts0.z); atomicAdd(&s_sum[c0 + 3], ts0.w);
    atomicAdd(&s_sum[128 + c0 + 0], ts1.x); atomicAdd(&s_sum[128 + c0 + 1], ts1.y);
    atomicAdd(&s_sum[128 + c0 + 2], ts1.z); atomicAdd(&s_sum[128 + c0 + 3], ts1.w);
    atomicAdd(&s_sq[c0 + 0], tq0.x); atomicAdd(&s_sq[c0 + 1], tq0.y);
    atomicAdd(&s_sq[c0 + 2], tq0.z); atomicAdd(&s_sq[c0 + 3], tq0.w);
    atomicAdd(&s_sq[128 + c0 + 0], tq1.x); atomicAdd(&s_sq[128 + c0 + 1], tq1.y);
    atomicAdd(&s_sq[128 + c0 + 2], tq1.z); atomicAdd(&s_sq[128 + c0 + 3], tq1.w);
    __syncthreads();

    atomicAdd(&g_sum[tid],   s_sum[tid]);
    atomicAdd(&g_sumsq[tid], s_sq[tid]);
}

// ---------------- 7) output: y = relu(agg*scale + shift), BN params fused -
__global__ void __launch_bounds__(256) output_kernel(const float* __restrict__ gamma,
                                                     const float* __restrict__ beta,
                                                     float* __restrict__ out) {
    __shared__ float s_scale[D];
    __shared__ float s_shift[D];
    {
        int t = threadIdx.x;
        float invN = 1.0f / (float)N_NODES;
        float mean = g_sum[t] * invN;
        float var  = g_sumsq[t] * invN - mean * mean;
        float sc   = gamma[t] * rsqrtf(var + BN_EPS);
        s_scale[t] = sc;
        s_shift[t] = beta[t] - mean * sc;
    }
    __syncthreads();

    const int total4 = N_NODES * D / 4;
    int i = blockIdx.x * blockDim.x + threadIdx.x;
    if (i >= total4) return;
    int c = (i & 63) * 4;
    float4 v  = reinterpret_cast<const float4*>(g_agg)[i];
    float4 sc = *reinterpret_cast<const float4*>(s_scale + c);
    float4 sh = *reinterpret_cast<const float4*>(s_shift + c);
    float4 y;
    y.x = fmaxf(fmaf(v.x, sc.x, sh.x), 0.0f);
    y.y = fmaxf(fmaf(v.y, sc.y, sh.y), 0.0f);
    y.z = fmaxf(fmaf(v.z, sc.z, sh.z), 0.0f);
    y.w = fmaxf(fmaf(v.w, sc.w, sh.w), 0.0f);
    reinterpret_cast<float4*>(out)[i] = y;
}

// ---------------- launch ----------------
extern "C" void kernel_launch(void* const* d_in, const int* in_sizes, int n_in,
                              void* d_out, int out_size) {
    const float* x     = (const float*)d_in[0];
    const int*   ei    = (const int*)d_in[1];     // int32 (JAX x64 disabled)
    const float* W     = (const float*)d_in[2];
    const float* bias  = (const float*)d_in[3];
    const float* gamma = (const float*)d_in[4];
    const float* beta  = (const float*)d_in[5];
    const int*   row   = ei;
    const int*   col   = ei + N_EDGES;
    float* out = (float*)d_out;

    init_kernel<<<(N_NODES + 255) / 256, 256>>>(W);
    count_kernel<<<(N_EDGES / 4 + 255) / 256, 256>>>(col);
    scan_kernel<<<SCAN_NB, 256>>>();
    fill_kernel<<<(N_EDGES + 255) / 256, 256>>>(row, col);

    dim3 gemm_grid((N_NODES + 63) / 64, D / 128);
    gemm_kernel<<<gemm_grid, 256>>>(x);

    aggregate_kernel<<<592, 256>>>(bias);

    output_kernel<<<(N_NODES * D / 4 + 255) / 256, 256>>>(gamma, beta, out);
}

// round 15
// speedup vs baseline: 1.1881x; 1.1881x over previous
#include <cuda_runtime.h>
#include <cuda_bf16.h>
#include <cstdint>

#define N_NODES 50000
#define N_EDGES 800000
#define D 256
#define BN_EPS 1e-5f
#define SCAN_NB 196            // ceil(50000/256)

// ---------------- scratch (device globals: allocation-free) ----------------
__device__ int   g_cnt[N_NODES];
__device__ int   g_fill[N_NODES];
__device__ int   g_off[N_NODES];
__device__ int   g_csr_src[N_EDGES];
__device__ float g_dinv[N_NODES];
__device__ int   g_part[256];
__device__ int   g_partpref[256];
__device__ __nv_bfloat16 g_whi[D * D];
__device__ __nv_bfloat16 g_wlo[D * D];
__device__ float g_hprime[(size_t)N_NODES * D];   // raw h = x @ W^T (no dinv)
__device__ float g_agg[(size_t)N_NODES * D];
__device__ float g_sum[D];
__device__ float g_sumsq[D];

__device__ __forceinline__ unsigned pack_bf2(float a, float b) {
    __nv_bfloat162 p = __floats2bfloat162_rn(a, b);
    return *reinterpret_cast<unsigned*>(&p);
}

// ---------------- 1) init counters + BN sums + W hi/lo split --------------
__global__ void init_kernel(const float* __restrict__ W) {
    int i = blockIdx.x * blockDim.x + threadIdx.x;
    if (i < N_NODES) { g_cnt[i] = 0; g_fill[i] = 0; }
    if (i < D) { g_sum[i] = 0.0f; g_sumsq[i] = 0.0f; }
    if (i < D * D / 4) {
        float4 v = reinterpret_cast<const float4*>(W)[i];
        float hx = __bfloat162float(__float2bfloat16(v.x));
        float hy = __bfloat162float(__float2bfloat16(v.y));
        float hz = __bfloat162float(__float2bfloat16(v.z));
        float hw = __bfloat162float(__float2bfloat16(v.w));
        uint2 hi = make_uint2(pack_bf2(v.x, v.y), pack_bf2(v.z, v.w));
        uint2 lo = make_uint2(pack_bf2(v.x - hx, v.y - hy), pack_bf2(v.z - hz, v.w - hw));
        reinterpret_cast<uint2*>(g_whi)[i] = hi;
        reinterpret_cast<uint2*>(g_wlo)[i] = lo;
    }
}

// ---------------- 2) in-degree count (int4 vectorized) --------------------
__global__ void count_kernel(const int* __restrict__ col) {
    int i = blockIdx.x * blockDim.x + threadIdx.x;
    if (i >= N_EDGES / 4) return;
    int4 c = reinterpret_cast<const int4*>(col)[i];
    atomicAdd(&g_cnt[c.x], 1);
    atomicAdd(&g_cnt[c.y], 1);
    atomicAdd(&g_cnt[c.z], 1);
    atomicAdd(&g_cnt[c.w], 1);
}

// ---------------- 3a) per-block sums ----------------
__global__ void __launch_bounds__(256) blocksum_kernel() {
    const int tid  = threadIdx.x;
    const int lane = tid & 31;
    const int wid  = tid >> 5;
    int i = blockIdx.x * 256 + tid;
    int v = (i < N_NODES) ? g_cnt[i] : 0;
#pragma unroll
    for (int ofs = 16; ofs > 0; ofs >>= 1)
        v += __shfl_down_sync(0xffffffffu, v, ofs);
    __shared__ int ws[8];
    if (lane == 0) ws[wid] = v;
    __syncthreads();
    if (tid == 0) {
        int s = 0;
#pragma unroll
        for (int w = 0; w < 8; w++) s += ws[w];
        g_part[blockIdx.x] = s;
    }
}

// ---------------- 3b) scan of partials ----------------
__global__ void __launch_bounds__(256) partscan_kernel() {
    __shared__ int sm[256];
    const int tid = threadIdx.x;
    int v = (tid < SCAN_NB) ? g_part[tid] : 0;
    sm[tid] = v;
    __syncthreads();
#pragma unroll
    for (int ofs = 1; ofs < 256; ofs <<= 1) {
        int t = (tid >= ofs) ? sm[tid - ofs] : 0;
        __syncthreads();
        sm[tid] += t;
        __syncthreads();
    }
    if (tid < SCAN_NB) g_partpref[tid] = sm[tid] - v;
}

// ---------------- 3c) offsets + dinv ----------------
__global__ void __launch_bounds__(256) offsets_kernel() {
    __shared__ int sm[256];
    const int tid = threadIdx.x;
    int i = blockIdx.x * 256 + tid;
    int v = (i < N_NODES) ? g_cnt[i] : 0;
    sm[tid] = v;
    __syncthreads();
#pragma unroll
    for (int ofs = 1; ofs < 256; ofs <<= 1) {
        int t = (tid >= ofs) ? sm[tid - ofs] : 0;
        __syncthreads();
        sm[tid] += t;
        __syncthreads();
    }
    if (i < N_NODES) {
        g_off[i]  = sm[tid] - v + g_partpref[blockIdx.x];
        g_dinv[i] = rsqrtf((float)(v + 1));
    }
}

// ---------------- 4) fill CSR ----------------
__global__ void fill_kernel(const int* __restrict__ row,
                            const int* __restrict__ col) {
    int e = blockIdx.x * blockDim.x + threadIdx.x;
    if (e >= N_EDGES) return;
    int src = row[e];
    int dst = col[e];
    int pos = g_off[dst] + atomicAdd(&g_fill[dst], 1);
    g_csr_src[pos] = src;
}

// ---------------- 5) tensor-core GEMM: h = x @ W^T (no dinv) --------------
// 3xBF16 split on mma.sync.m16n8k16, in-register A split, ldmatrix frags.
// BM=64, BN=128, BK=32. 8 warps: wm = (wid&1)*32, wn = (wid>>1)*32.
#define APAD 40

__device__ __forceinline__ void mma_bf16(float* c, const unsigned* a, const unsigned* b) {
    asm volatile(
        "mma.sync.aligned.m16n8k16.row.col.f32.bf16.bf16.f32 "
        "{%0,%1,%2,%3}, {%4,%5,%6,%7}, {%8,%9}, {%0,%1,%2,%3};"
        : "+f"(c[0]), "+f"(c[1]), "+f"(c[2]), "+f"(c[3])
        : "r"(a[0]), "r"(a[1]), "r"(a[2]), "r"(a[3]), "r"(b[0]), "r"(b[1]));
}
__device__ __forceinline__ void ldmx4(unsigned* r, unsigned addr) {
    asm volatile("ldmatrix.sync.aligned.m8n8.x4.shared.b16 {%0,%1,%2,%3}, [%4];"
                 : "=r"(r[0]), "=r"(r[1]), "=r"(r[2]), "=r"(r[3]) : "r"(addr));
}
__device__ __forceinline__ void ldmx2(unsigned* r, unsigned addr) {
    asm volatile("ldmatrix.sync.aligned.m8n8.x2.shared.b16 {%0,%1}, [%2];"
                 : "=r"(r[0]), "=r"(r[1]) : "r"(addr));
}
__device__ __forceinline__ unsigned s2u(const void* p) {
    return (unsigned)__cvta_generic_to_shared(p);
}
__device__ __forceinline__ void split4(float4 v, uint2& hi, uint2& lo) {
    float hx = __bfloat162float(__float2bfloat16(v.x));
    float hy = __bfloat162float(__float2bfloat16(v.y));
    float hz = __bfloat162float(__float2bfloat16(v.z));
    float hw = __bfloat162float(__float2bfloat16(v.w));
    hi = make_uint2(pack_bf2(v.x, v.y), pack_bf2(v.z, v.w));
    lo = make_uint2(pack_bf2(v.x - hx, v.y - hy), pack_bf2(v.z - hz, v.w - hw));
}

__global__ void __launch_bounds__(256) gemm_kernel(const float* __restrict__ x) {
    __shared__ __nv_bfloat16 As_hi[64][APAD];
    __shared__ __nv_bfloat16 As_lo[64][APAD];
    __shared__ __nv_bfloat16 Bs_hi[128][APAD];
    __shared__ __nv_bfloat16 Bs_lo[128][APAD];

    const int brow = blockIdx.x * 64;
    const int bcol = blockIdx.y * 128;
    const int tid  = threadIdx.x;
    const int lane = tid & 31;
    const int wid  = tid >> 5;
    const int wm   = (wid & 1) * 32;
    const int wn   = (wid >> 1) * 32;
    const int lr   = lane & 7;
    const int grp  = lane >> 3;

    float acc[2][4][4];
#pragma unroll
    for (int mi = 0; mi < 2; mi++)
#pragma unroll
        for (int ni = 0; ni < 4; ni++)
#pragma unroll
            for (int r = 0; r < 4; r++) acc[mi][ni][r] = 0.0f;

    const int arow = tid >> 2;
    const int acol = (tid & 3) * 8;
    const bool avalid = (brow + arow < N_NODES);
    const float* xrow = x + (size_t)(brow + arow) * D + acol;
    const int br0 = tid >> 2,          bc0 = (tid & 3) * 8;
    const int br1 = (tid + 256) >> 2,  bc1 = ((tid + 256) & 3) * 8;
    const __nv_bfloat16* wh0 = g_whi + (size_t)(bcol + br0) * D + bc0;
    const __nv_bfloat16* wl0 = g_wlo + (size_t)(bcol + br0) * D + bc0;
    const __nv_bfloat16* wh1 = g_whi + (size_t)(bcol + br1) * D + bc1;
    const __nv_bfloat16* wl1 = g_wlo + (size_t)(bcol + br1) * D + bc1;

    const float4 zf4 = make_float4(0.f, 0.f, 0.f, 0.f);
    float4 sa0, sa1;
    uint4  sbh0, sbl0, sbh1, sbl1;

    sa0  = avalid ? *reinterpret_cast<const float4*>(xrow)     : zf4;
    sa1  = avalid ? *reinterpret_cast<const float4*>(xrow + 4) : zf4;
    sbh0 = *reinterpret_cast<const uint4*>(wh0);
    sbl0 = *reinterpret_cast<const uint4*>(wl0);
    sbh1 = *reinterpret_cast<const uint4*>(wh1);
    sbl1 = *reinterpret_cast<const uint4*>(wl1);

    for (int kb = 0; kb < D; kb += 32) {
        {
            uint2 h0, l0, h1, l1;
            split4(sa0, h0, l0);
            split4(sa1, h1, l1);
            *reinterpret_cast<uint4*>(&As_hi[arow][acol]) = make_uint4(h0.x, h0.y, h1.x, h1.y);
            *reinterpret_cast<uint4*>(&As_lo[arow][acol]) = make_uint4(l0.x, l0.y, l1.x, l1.y);
            *reinterpret_cast<uint4*>(&Bs_hi[br0][bc0]) = sbh0;
            *reinterpret_cast<uint4*>(&Bs_lo[br0][bc0]) = sbl0;
            *reinterpret_cast<uint4*>(&Bs_hi[br1][bc1]) = sbh1;
            *reinterpret_cast<uint4*>(&Bs_lo[br1][bc1]) = sbl1;
        }
        __syncthreads();

        if (kb + 32 < D) {
            int nk = kb + 32;
            sa0  = avalid ? *reinterpret_cast<const float4*>(xrow + nk)     : zf4;
            sa1  = avalid ? *reinterpret_cast<const float4*>(xrow + nk + 4) : zf4;
            sbh0 = *reinterpret_cast<const uint4*>(wh0 + nk);
            sbl0 = *reinterpret_cast<const uint4*>(wl0 + nk);
            sbh1 = *reinterpret_cast<const uint4*>(wh1 + nk);
            sbl1 = *reinterpret_cast<const uint4*>(wl1 + nk);
        }

#pragma unroll
        for (int kk = 0; kk < 32; kk += 16) {
            unsigned ahi[2][4], alo[2][4], bhi[4][2], blo[4][2];
            const int ar = ((grp & 1) << 3) + lr;
            const int ac = kk + ((grp >> 1) << 3);
#pragma unroll
            for (int mi = 0; mi < 2; mi++) {
                ldmx4(ahi[mi], s2u(&As_hi[wm + mi * 16 + ar][ac]));
                ldmx4(alo[mi], s2u(&As_lo[wm + mi * 16 + ar][ac]));
            }
            const int bc = kk + ((lane >> 3) & 1) * 8;
#pragma unroll
            for (int ni = 0; ni < 4; ni++) {
                ldmx2(bhi[ni], s2u(&Bs_hi[wn + ni * 8 + lr][bc]));
                ldmx2(blo[ni], s2u(&Bs_lo[wn + ni * 8 + lr][bc]));
            }
#pragma unroll
            for (int mi = 0; mi < 2; mi++)
#pragma unroll
                for (int ni = 0; ni < 4; ni++) {
                    mma_bf16(acc[mi][ni], ahi[mi], bhi[ni]);
                    mma_bf16(acc[mi][ni], alo[mi], bhi[ni]);
                    mma_bf16(acc[mi][ni], ahi[mi], blo[ni]);
                }
        }
        __syncthreads();
    }

    // epilogue: store raw h (no dinv — moved into aggregate)
    const int qr = lane >> 2;
    const int qc = lane & 3;
#pragma unroll
    for (int mi = 0; mi < 2; mi++) {
        int r0 = brow + wm + mi * 16 + qr;
        int r1 = r0 + 8;
#pragma unroll
        for (int ni = 0; ni < 4; ni++) {
            int c = bcol + wn + ni * 8 + qc * 2;
            if (r0 < N_NODES) {
                float2 v = make_float2(acc[mi][ni][0], acc[mi][ni][1]);
                *reinterpret_cast<float2*>(g_hprime + (size_t)r0 * D + c) = v;
            }
            if (r1 < N_NODES) {
                float2 v = make_float2(acc[mi][ni][2], acc[mi][ni][3]);
                *reinterpret_cast<float2*>(g_hprime + (size_t)r1 * D + c) = v;
            }
        }
    }
}

// ---------------- 6) gather-aggregate (dinv-weighted) + BN stats ----------
// agg[c] = dinv[c] * ( dinv[c]*h[c] + sum_src dinv[src]*h[src] ) + bias
__device__ __forceinline__ void fma4(float4& a, const float4& u, float w) {
    a.x = fmaf(u.x, w, a.x); a.y = fmaf(u.y, w, a.y);
    a.z = fmaf(u.z, w, a.z); a.w = fmaf(u.w, w, a.w);
}
__device__ __forceinline__ void acc4(float4& a, const float4& b) {
    a.x += b.x; a.y += b.y; a.z += b.z; a.w += b.w;
}

__global__ void __launch_bounds__(256) aggregate_kernel(const float* __restrict__ bias) {
    __shared__ float s_sum[D];
    __shared__ float s_sq[D];
    const int tid  = threadIdx.x;
    const int lane = tid & 31;
    const int wid  = tid >> 5;
    s_sum[tid] = 0.0f;
    s_sq[tid]  = 0.0f;
    __syncthreads();

    const float4* hp4 = reinterpret_cast<const float4*>(g_hprime);
    float4*       out4 = reinterpret_cast<float4*>(g_agg);
    const float4* b4   = reinterpret_cast<const float4*>(bias);
    const float4 bb0 = b4[lane];
    const float4 bb1 = b4[lane + 32];

    float4 ts0 = make_float4(0.f, 0.f, 0.f, 0.f);
    float4 ts1 = make_float4(0.f, 0.f, 0.f, 0.f);
    float4 tq0 = make_float4(0.f, 0.f, 0.f, 0.f);
    float4 tq1 = make_float4(0.f, 0.f, 0.f, 0.f);

    const int warp0  = blockIdx.x * 8 + wid;
    const int nwarps = gridDim.x * 8;

    for (int c = warp0; c < N_NODES; c += nwarps) {
        const float dvc = g_dinv[c];
        // self-loop: dinv[c] * h[c]
        float4 h0 = hp4[(size_t)c * 64 + lane];
        float4 h1 = hp4[(size_t)c * 64 + lane + 32];
        float4 a0 = make_float4(h0.x * dvc, h0.y * dvc, h0.z * dvc, h0.w * dvc);
        float4 a1 = make_float4(h1.x * dvc, h1.y * dvc, h1.z * dvc, h1.w * dvc);
        float4 e0 = make_float4(0.f, 0.f, 0.f, 0.f);
        float4 e1 = make_float4(0.f, 0.f, 0.f, 0.f);

        const int beg = g_off[c];
        const int end = beg + g_cnt[c];
        int e = beg;
        for (; e + 1 < end; e += 2) {
            int s0 = g_csr_src[e];
            int s1 = g_csr_src[e + 1];
            float w0 = g_dinv[s0];
            float w1 = g_dinv[s1];
            const float4* p0 = hp4 + (size_t)s0 * 64;
            const float4* p1 = hp4 + (size_t)s1 * 64;
            float4 u0 = p0[lane], u1 = p0[lane + 32];
            float4 v0 = p1[lane], v1 = p1[lane + 32];
            fma4(a0, u0, w0); fma4(a1, u1, w0);
            fma4(e0, v0, w1); fma4(e1, v1, w1);
        }
        if (e < end) {
            int s0 = g_csr_src[e];
            float w0 = g_dinv[s0];
            const float4* p0 = hp4 + (size_t)s0 * 64;
            fma4(a0, p0[lane], w0); fma4(a1, p0[lane + 32], w0);
        }
        acc4(a0, e0); acc4(a1, e1);

        a0.x = fmaf(a0.x, dvc, bb0.x); a0.y = fmaf(a0.y, dvc, bb0.y);
        a0.z = fmaf(a0.z, dvc, bb0.z); a0.w = fmaf(a0.w, dvc, bb0.w);
        a1.x = fmaf(a1.x, dvc, bb1.x); a1.y = fmaf(a1.y, dvc, bb1.y);
        a1.z = fmaf(a1.z, dvc, bb1.z); a1.w = fmaf(a1.w, dvc, bb1.w);

        out4[(size_t)c * 64 + lane]      = a0;
        out4[(size_t)c * 64 + lane + 32] = a1;

        acc4(ts0, a0); acc4(ts1, a1);
        tq0.x = fmaf(a0.x, a0.x, tq0.x); tq0.y = fmaf(a0.y, a0.y, tq0.y);
        tq0.z = fmaf(a0.z, a0.z, tq0.z); tq0.w = fmaf(a0.w, a0.w, tq0.w);
        tq1.x = fmaf(a1.x, a1.x, tq1.x); tq1.y = fmaf(a1.y, a1.y, tq1.y);
        tq1.z = fmaf(a1.z, a1.z, tq1.z); tq1.w = fmaf(a1.w, a1.w, tq1.w);
    }

    const int c0 = 4 * lane;
    atomicAdd(&s_sum[c0 + 0], ts0.x); atomicAdd(&s_sum[c0 + 1], ts0.y);
    atomicAdd(&s_sum[c0 + 2], ts0.z); atomicAdd(&s_sum[c0 + 3], ts0.w);
    atomicAdd(&s_sum[128 + c0 + 0], ts1.x); atomicAdd(&s_sum[128 + c0 + 1], ts1.y);
    atomicAdd(&s_sum[128 + c0 + 2], ts1.z); atomicAdd(&s_sum[128 + c0 + 3], ts1.w);
    atomicAdd(&s_sq[c0 + 0], tq0.x); atomicAdd(&s_sq[c0 + 1], tq0.y);
    atomicAdd(&s_sq[c0 + 2], tq0.z); atomicAdd(&s_sq[c0 + 3], tq0.w);
    atomicAdd(&s_sq[128 + c0 + 0], tq1.x); atomicAdd(&s_sq[128 + c0 + 1], tq1.y);
    atomicAdd(&s_sq[128 + c0 + 2], tq1.z); atomicAdd(&s_sq[128 + c0 + 3], tq1.w);
    __syncthreads();

    atomicAdd(&g_sum[tid],   s_sum[tid]);
    atomicAdd(&g_sumsq[tid], s_sq[tid]);
}

// ---------------- 7) output: y = relu(agg*scale + shift), BN fused --------
__global__ void __launch_bounds__(256) output_kernel(const float* __restrict__ gamma,
                                                     const float* __restrict__ beta,
                                                     float* __restrict__ out) {
    __shared__ float s_scale[D];
    __shared__ float s_shift[D];
    {
        int t = threadIdx.x;
        float invN = 1.0f / (float)N_NODES;
        float mean = g_sum[t] * invN;
        float var  = g_sumsq[t] * invN - mean * mean;
        float sc   = gamma[t] * rsqrtf(var + BN_EPS);
        s_scale[t] = sc;
        s_shift[t] = beta[t] - mean * sc;
    }
    __syncthreads();

    const int total4 = N_NODES * D / 4;
    int i = blockIdx.x * blockDim.x + threadIdx.x;
    if (i >= total4) return;
    int c = (i & 63) * 4;
    float4 v  = reinterpret_cast<const float4*>(g_agg)[i];
    float4 sc = *reinterpret_cast<const float4*>(s_scale + c);
    float4 sh = *reinterpret_cast<const float4*>(s_shift + c);
    float4 y;
    y.x = fmaxf(fmaf(v.x, sc.x, sh.x), 0.0f);
    y.y = fmaxf(fmaf(v.y, sc.y, sh.y), 0.0f);
    y.z = fmaxf(fmaf(v.z, sc.z, sh.z), 0.0f);
    y.w = fmaxf(fmaf(v.w, sc.w, sh.w), 0.0f);
    reinterpret_cast<float4*>(out)[i] = y;
}

// ---------------- launch: fork GEMM parallel to CSR chain -----------------
extern "C" void kernel_launch(void* const* d_in, const int* in_sizes, int n_in,
                              void* d_out, int out_size) {
    const float* x     = (const float*)d_in[0];
    const int*   ei    = (const int*)d_in[1];     // int32 (JAX x64 disabled)
    const float* W     = (const float*)d_in[2];
    const float* bias  = (const float*)d_in[3];
    const float* gamma = (const float*)d_in[4];
    const float* beta  = (const float*)d_in[5];
    const int*   row   = ei;
    const int*   col   = ei + N_EDGES;
    float* out = (float*)d_out;

    static cudaStream_t s1 = nullptr;
    static cudaEvent_t  evFork = nullptr, evJoin = nullptr;
    if (s1 == nullptr) {
        cudaStreamCreateWithFlags(&s1, cudaStreamNonBlocking);
        cudaEventCreateWithFlags(&evFork, cudaEventDisableTiming);
        cudaEventCreateWithFlags(&evJoin, cudaEventDisableTiming);
    }

    // init on main stream (produces W split + zeroed counters)
    init_kernel<<<(N_NODES + 255) / 256, 256>>>(W);

    // fork: GEMM (depends only on init) runs on s1 ...
    cudaEventRecord(evFork, 0);
    cudaStreamWaitEvent(s1, evFork, 0);
    dim3 gemm_grid((N_NODES + 63) / 64, D / 128);
    gemm_kernel<<<gemm_grid, 256, 0, s1>>>(x);
    cudaEventRecord(evJoin, s1);

    // ... while the CSR chain runs on the main stream
    count_kernel<<<(N_EDGES / 4 + 255) / 256, 256>>>(col);
    blocksum_kernel<<<SCAN_NB, 256>>>();
    partscan_kernel<<<1, 256>>>();
    offsets_kernel<<<SCAN_NB, 256>>>();
    fill_kernel<<<(N_EDGES + 255) / 256, 256>>>(row, col);

    // join: aggregate needs both branches
    cudaStreamWaitEvent(0, evJoin, 0);
    aggregate_kernel<<<592, 256>>>(bias);

    output_kernel<<<(N_NODES * D / 4 + 255) / 256, 256>>>(gamma, beta, out);
}